// round 1
// baseline (speedup 1.0000x reference)
#include <cuda_runtime.h>
#include <cuda_bf16.h>
#include <math.h>

// Model dims
#define Bn 64
#define Sn 512
#define Tn 64
#define En 128
#define NHn 4
#define HDn 32
#define NLn 2
#define FFn 256
#define VOUTn 32000
#define TD (Tn-1)            // 63 decode steps
#define MROWS (Bn*Sn)        // 32768
#define DROWS (TD*Bn)        // 4032

// -------------------- scratch (device globals; no allocs allowed) --------------------
__device__ float g_x[MROWS*En];        // activations [B*S, E]
__device__ float g_qkv[MROWS*3*En];    // qkv [B*S, 384]
__device__ float g_ctx[MROWS*En];      // attention ctx / ff2 out
__device__ float g_ffh[MROWS*FFn];     // ff hidden / attn proj out
__device__ float g_h0[Bn*En];
__device__ float g_embx[DROWS*En];     // decoder input embeddings, row = t*64+b
__device__ float g_gatesx[DROWS*4*En]; // precomputed input gates
__device__ float g_hall[DROWS*En];     // all hidden states, row = t*64+b

// -------------------- embedding gathers --------------------
__global__ void gather_src_kernel(const int* __restrict__ src,
                                  const float* __restrict__ emb,
                                  float* __restrict__ out) {
    int n = blockIdx.x;                 // 0..32767 = b*512+s
    int tok = src[n];
    ((float4*)(out + (size_t)n*En))[threadIdx.x] =
        ((const float4*)(emb + (size_t)tok*En))[threadIdx.x];
}

__global__ void gather_trg_kernel(const int* __restrict__ trg,
                                  const float* __restrict__ emb,
                                  float* __restrict__ out) {
    int r = blockIdx.x;                 // r = t*64 + b
    int t = r >> 6, b = r & 63;
    int tok = trg[b*Tn + t];
    ((float4*)(out + (size_t)r*En))[threadIdx.x] =
        ((const float4*)(emb + (size_t)tok*En))[threadIdx.x];
}

// -------------------- generic fp32 GEMM: C[M,N] = A[M,K] @ B[N,K]^T + bias --------------------
// 128x128 tile, BK=16, 256 threads, 8x8 per-thread register tile.
#define GBM 128
#define GBN 128
#define GBK 16

template<int RELU, int PERMUTE>
__global__ __launch_bounds__(256)
void gemm_kernel(const float* __restrict__ A, const float* __restrict__ B,
                 const float* __restrict__ bias1, const float* __restrict__ bias2,
                 float* __restrict__ C, int M, int N, int K) {
    __shared__ float As[GBK][GBM];
    __shared__ float Bs[GBK][GBN];
    int tid = threadIdx.x;
    int tx = tid & 15, ty = tid >> 4;
    int rowBase = blockIdx.y * GBM;
    int colBase = blockIdx.x * GBN;

    float acc[8][8];
    #pragma unroll
    for (int i = 0; i < 8; i++)
        #pragma unroll
        for (int j = 0; j < 8; j++) acc[i][j] = 0.f;

    for (int k0 = 0; k0 < K; k0 += GBK) {
        // load A/B tiles (transposed into smem). 512 float4 per matrix, 2 per thread.
        #pragma unroll
        for (int i = 0; i < 2; i++) {
            int f = tid + i*256;
            int r = f >> 2, c4 = (f & 3) * 4;
            int gr = rowBase + r;
            float4 v = make_float4(0.f,0.f,0.f,0.f);
            if (gr < M) v = *(const float4*)(A + (size_t)gr*K + k0 + c4);
            As[c4+0][r] = v.x; As[c4+1][r] = v.y; As[c4+2][r] = v.z; As[c4+3][r] = v.w;
            int gc = colBase + r;
            float4 w = make_float4(0.f,0.f,0.f,0.f);
            if (gc < N) w = *(const float4*)(B + (size_t)gc*K + k0 + c4);
            Bs[c4+0][r] = w.x; Bs[c4+1][r] = w.y; Bs[c4+2][r] = w.z; Bs[c4+3][r] = w.w;
        }
        __syncthreads();
        #pragma unroll
        for (int kk = 0; kk < GBK; kk++) {
            float a[8], b[8];
            *(float4*)&a[0] = *(const float4*)&As[kk][ty*8];
            *(float4*)&a[4] = *(const float4*)&As[kk][ty*8+4];
            *(float4*)&b[0] = *(const float4*)&Bs[kk][tx*8];
            *(float4*)&b[4] = *(const float4*)&Bs[kk][tx*8+4];
            #pragma unroll
            for (int i = 0; i < 8; i++)
                #pragma unroll
                for (int j = 0; j < 8; j++)
                    acc[i][j] += a[i] * b[j];
        }
        __syncthreads();
    }

    // epilogue
    #pragma unroll
    for (int i = 0; i < 8; i++) {
        int row = rowBase + ty*8 + i;
        if (row < M) {
            #pragma unroll
            for (int j4 = 0; j4 < 2; j4++) {
                float4 v;
                float* vp = &v.x;
                #pragma unroll
                for (int j = 0; j < 4; j++) {
                    int col = colBase + tx*8 + j4*4 + j;
                    float val = acc[i][j4*4 + j];
                    if (bias1) val += bias1[col];
                    if (bias2) val += bias2[col];
                    if (RELU) val = fmaxf(val, 0.f);
                    vp[j] = val;
                }
                size_t off;
                if (PERMUTE) {
                    // row = t*64+b  ->  out[(b*63+t), col]
                    int t = row >> 6, b = row & 63;
                    off = ((size_t)(b*TD + t))*N + colBase + tx*8 + j4*4;
                } else {
                    off = (size_t)row*N + colBase + tx*8 + j4*4;
                }
                *(float4*)(C + off) = v;
            }
        }
    }
}

// -------------------- fused flash-style attention --------------------
// grid = B*NH*(S/128) = 1024 blocks, 128 threads, one thread per query row.
__global__ __launch_bounds__(128)
void attn_kernel(const float* __restrict__ qkv, float* __restrict__ ctx) {
    int blk = blockIdx.x;
    int qc = blk & 3;
    int h  = (blk >> 2) & 3;
    int b  = blk >> 4;
    int qi = qc*128 + threadIdx.x;
    const float* base = qkv + ((size_t)b*Sn)*(3*En);

    float q[32];
    {
        const float4* qp = (const float4*)(base + (size_t)qi*(3*En) + h*HDn);
        #pragma unroll
        for (int i = 0; i < 8; i++) {
            float4 v = qp[i];
            q[4*i+0]=v.x; q[4*i+1]=v.y; q[4*i+2]=v.z; q[4*i+3]=v.w;
        }
    }

    __shared__ float Ks[64][32];
    __shared__ float Vs[64][32];

    float m = -1e30f, l = 0.f;
    float acc[32];
    #pragma unroll
    for (int d = 0; d < 32; d++) acc[d] = 0.f;

    const float scale = 0.17677669529663689f;  // 1/sqrt(32)

    for (int s0 = 0; s0 < Sn; s0 += 64) {
        __syncthreads();
        for (int i = threadIdx.x; i < 64*8; i += 128) {
            int r = i >> 3, c4 = (i & 7) * 4;
            const float* rowp = base + (size_t)(s0 + r)*(3*En) + h*HDn;
            *(float4*)&Ks[r][c4] = *(const float4*)(rowp + En   + c4);
            *(float4*)&Vs[r][c4] = *(const float4*)(rowp + 2*En + c4);
        }
        __syncthreads();
        #pragma unroll 4
        for (int j = 0; j < 64; j++) {
            float s = 0.f;
            #pragma unroll
            for (int d = 0; d < 32; d++) s += q[d]*Ks[j][d];
            s *= scale;
            if (s > m) {
                float corr = __expf(m - s);
                m = s; l *= corr;
                #pragma unroll
                for (int d = 0; d < 32; d++) acc[d] *= corr;
            }
            float p = __expf(s - m);
            l += p;
            #pragma unroll
            for (int d = 0; d < 32; d++) acc[d] += p * Vs[j][d];
        }
    }
    float inv = 1.f / l;
    float* op = ctx + ((size_t)(b*Sn + qi))*En + h*HDn;
    #pragma unroll
    for (int i = 0; i < 8; i++) {
        float4 v = make_float4(acc[4*i]*inv, acc[4*i+1]*inv, acc[4*i+2]*inv, acc[4*i+3]*inv);
        ((float4*)op)[i] = v;
    }
}

// -------------------- residual add + layernorm (in-place on x) --------------------
__global__ __launch_bounds__(128)
void add_ln_kernel(float* __restrict__ x, const float* __restrict__ y,
                   const float* __restrict__ w, const float* __restrict__ bb) {
    int r = blockIdx.x, e = threadIdx.x;
    size_t idx = (size_t)r*En + e;
    float v = x[idx] + y[idx];

    __shared__ float red[4];
    float s = v;
    #pragma unroll
    for (int o = 16; o; o >>= 1) s += __shfl_xor_sync(0xffffffffu, s, o);
    if ((e & 31) == 0) red[e >> 5] = s;
    __syncthreads();
    float mu = (red[0]+red[1]+red[2]+red[3]) * (1.f/En);
    __syncthreads();
    float d = v - mu;
    s = d*d;
    #pragma unroll
    for (int o = 16; o; o >>= 1) s += __shfl_xor_sync(0xffffffffu, s, o);
    if ((e & 31) == 0) red[e >> 5] = s;
    __syncthreads();
    float var = (red[0]+red[1]+red[2]+red[3]) * (1.f/En);
    x[idx] = d * rsqrtf(var + 1e-5f) * w[e] + bb[e];
}

// -------------------- h0 = mean over S --------------------
__global__ __launch_bounds__(128)
void mean_kernel(const float* __restrict__ x, float* __restrict__ h0) {
    int b = blockIdx.x, e = threadIdx.x;
    float s = 0.f;
    for (int i = 0; i < Sn; i++) s += x[((size_t)b*Sn + i)*En + e];
    h0[b*En + e] = s * (1.f/Sn);
}

// -------------------- LSTM recurrence: one block per batch element --------------------
__device__ __forceinline__ float sigf(float x) { return 1.f / (1.f + __expf(-x)); }

__global__ __launch_bounds__(512)
void lstm_kernel(const float* __restrict__ gatesx, const float* __restrict__ w_hh,
                 const float* __restrict__ h0, float* __restrict__ hall) {
    __shared__ float hs[En];
    __shared__ float cs[En];
    __shared__ float gsm[4*En];
    int b = blockIdx.x;
    int k = threadIdx.x;           // gate index 0..511
    if (k < En) { hs[k] = h0[b*En + k]; cs[k] = 0.f; }
    __syncthreads();

    const float4* wrow = (const float4*)(w_hh + (size_t)k*En);
    const float4* h4p  = (const float4*)hs;

    for (int t = 0; t < TD; t++) {
        const float* gx = gatesx + ((size_t)(t*Bn + b))*(4*En);
        float acc = gx[k];
        #pragma unroll
        for (int e4 = 0; e4 < En/4; e4++) {
            float4 w4 = wrow[e4];
            float4 h4 = h4p[e4];
            acc += w4.x*h4.x + w4.y*h4.y + w4.z*h4.z + w4.w*h4.w;
        }
        gsm[k] = acc;
        __syncthreads();
        if (k < En) {
            float gi = gsm[k], gf = gsm[En+k], gg = gsm[2*En+k], go = gsm[3*En+k];
            float c = sigf(gf)*cs[k] + sigf(gi)*tanhf(gg);
            float h = sigf(go)*tanhf(c);
            cs[k] = c; hs[k] = h;
            hall[((size_t)(t*Bn + b))*En + k] = h;
        }
        __syncthreads();
    }
}

// -------------------- host launcher --------------------
extern "C" void kernel_launch(void* const* d_in, const int* in_sizes, int n_in,
                              void* d_out, int out_size) {
    const int*   src     = (const int*)  d_in[0];
    const int*   trg     = (const int*)  d_in[1];
    const float* emb_in  = (const float*)d_in[2];
    const float* emb_out = (const float*)d_in[3];
    const float* wqkv    = (const float*)d_in[4];
    const float* bqkv    = (const float*)d_in[5];
    const float* wo      = (const float*)d_in[6];
    const float* bo      = (const float*)d_in[7];
    const float* ln1w    = (const float*)d_in[8];
    const float* ln1b    = (const float*)d_in[9];
    const float* w1      = (const float*)d_in[10];
    const float* b1      = (const float*)d_in[11];
    const float* w2      = (const float*)d_in[12];
    const float* b2      = (const float*)d_in[13];
    const float* ln2w    = (const float*)d_in[14];
    const float* ln2b    = (const float*)d_in[15];
    const float* w_ih    = (const float*)d_in[16];
    const float* w_hh    = (const float*)d_in[17];
    const float* b_ih    = (const float*)d_in[18];
    const float* b_hh    = (const float*)d_in[19];
    const float* fc_w    = (const float*)d_in[20];
    const float* fc_b    = (const float*)d_in[21];
    float* out = (float*)d_out;

    float *x, *qkv, *ctx, *ffh, *h0, *embx, *gatesx, *hall;
    cudaGetSymbolAddress((void**)&x,      g_x);
    cudaGetSymbolAddress((void**)&qkv,    g_qkv);
    cudaGetSymbolAddress((void**)&ctx,    g_ctx);
    cudaGetSymbolAddress((void**)&ffh,    g_ffh);
    cudaGetSymbolAddress((void**)&h0,     g_h0);
    cudaGetSymbolAddress((void**)&embx,   g_embx);
    cudaGetSymbolAddress((void**)&gatesx, g_gatesx);
    cudaGetSymbolAddress((void**)&hall,   g_hall);

    // 1) embed src
    gather_src_kernel<<<MROWS, 32>>>(src, emb_in, x);

    // 2) encoder layers
    for (int l = 0; l < NLn; l++) {
        // qkv = x @ wqkv[l]^T + bqkv[l]   [32768, 384]
        gemm_kernel<0,0><<<dim3(3*En/GBN, MROWS/GBM), 256>>>(
            x, wqkv + (size_t)l*3*En*En, bqkv + l*3*En, nullptr, qkv, MROWS, 3*En, En);
        // attention -> ctx
        attn_kernel<<<Bn*NHn*(Sn/128), 128>>>(qkv, ctx);
        // proj: ffh = ctx @ wo[l]^T + bo[l]
        gemm_kernel<0,0><<<dim3(En/GBN, MROWS/GBM), 256>>>(
            ctx, wo + (size_t)l*En*En, bo + l*En, nullptr, ffh, MROWS, En, En);
        // x = LN(x + ffh)
        add_ln_kernel<<<MROWS, 128>>>(x, ffh, ln1w + l*En, ln1b + l*En);
        // ffh = relu(x @ w1[l]^T + b1[l])  [32768, 256]
        gemm_kernel<1,0><<<dim3(FFn/GBN, MROWS/GBM), 256>>>(
            x, w1 + (size_t)l*FFn*En, b1 + l*FFn, nullptr, ffh, MROWS, FFn, En);
        // ctx = ffh @ w2[l]^T + b2[l]  (K=256)
        gemm_kernel<0,0><<<dim3(En/GBN, MROWS/GBM), 256>>>(
            ffh, w2 + (size_t)l*En*FFn, b2 + l*En, nullptr, ctx, MROWS, En, FFn);
        // x = LN(x + ctx)
        add_ln_kernel<<<MROWS, 128>>>(x, ctx, ln2w + l*En, ln2b + l*En);
    }

    // 3) h0 = mean over S
    mean_kernel<<<Bn, 128>>>(x, h0);

    // 4) decoder input-side precompute: embx, then gatesx = embx @ w_ih^T + b_ih + b_hh
    gather_trg_kernel<<<DROWS, 32>>>(trg, emb_out, embx);
    gemm_kernel<0,0><<<dim3(4*En/GBN, (DROWS + GBM - 1)/GBM), 256>>>(
        embx, w_ih, b_ih, b_hh, gatesx, DROWS, 4*En, En);

    // 5) LSTM recurrence (parallel over batch)
    lstm_kernel<<<Bn, 512>>>(gatesx, w_hh, h0, hall);

    // 6) logits = hall @ fc_w^T + fc_b, permuted to [B, T-1, V]
    gemm_kernel<0,1><<<dim3(VOUTn/GBN, (DROWS + GBM - 1)/GBM), 256>>>(
        hall, fc_w, fc_b, nullptr, out, DROWS, VOUTn, En);
}